// round 4
// baseline (speedup 1.0000x reference)
#include <cuda_runtime.h>
#include <cuda_bf16.h>
#include <math_constants.h>

#define N 8192
#define D 64
#define LOG2E 1.4426950408889634f

// ---------------- scratch (static device memory; no allocation) ----------------
__device__ float g_Qx[N * D];
__device__ float g_Kx[N * D];
__device__ float g_Qy[N * D];
__device__ float g_Ky[N * D];
__device__ float g_xatt[N * D];
__device__ float g_yatt[N * D];
__device__ float g_xnrm[N];
__device__ float g_ynrm[N];

// ---------------- packed f32x2 helpers ----------------
__device__ __forceinline__ unsigned long long fma2_(unsigned long long a,
                                                    unsigned long long b,
                                                    unsigned long long c) {
    unsigned long long d;
    asm("fma.rn.f32x2 %0, %1, %2, %3;" : "=l"(d) : "l"(a), "l"(b), "l"(c));
    return d;
}
__device__ __forceinline__ unsigned long long mul2_(unsigned long long a,
                                                    unsigned long long b) {
    unsigned long long d;
    asm("mul.rn.f32x2 %0, %1, %2;" : "=l"(d) : "l"(a), "l"(b));
    return d;
}
__device__ __forceinline__ unsigned long long pk2(float lo, float hi) {
    unsigned long long r;
    asm("mov.b64 %0, {%1, %2};" : "=l"(r) : "f"(lo), "f"(hi));
    return r;
}
__device__ __forceinline__ float2 up2(unsigned long long v) {
    float lo, hi;
    asm("mov.b64 {%0, %1}, %2;" : "=f"(lo), "=f"(hi) : "l"(v));
    return make_float2(lo, hi);
}

// ---------------- kernel 1: projections Q = In@Wq * 0.125, K = In@Wk ----------------
// grid 4096 blocks x 256 threads; block handles 4 rows (covering x rows then y rows)
__global__ __launch_bounds__(256) void proj_kernel(const float* __restrict__ x,
                                                   const float* __restrict__ y,
                                                   const float* __restrict__ Wq,
                                                   const float* __restrict__ Wk) {
    __shared__ float sW[2][64][65];
    __shared__ float sIn[4][64];

    int tid = threadIdx.x;
    int base = blockIdx.x * 4;  // global row base (0..16380)

    const float* src;
    float *dstQ, *dstK;
    if (base < N) {
        src = x + (size_t)base * D;
        dstQ = g_Qx + (size_t)base * D;
        dstK = g_Kx + (size_t)base * D;
    } else {
        int b2 = base - N;
        src = y + (size_t)b2 * D;
        dstQ = g_Qy + (size_t)b2 * D;
        dstK = g_Ky + (size_t)b2 * D;
    }

    for (int idx = tid; idx < 4096; idx += 256) {
        sW[0][idx >> 6][idx & 63] = Wq[idx];
        sW[1][idx >> 6][idx & 63] = Wk[idx];
    }
    sIn[tid >> 6][tid & 63] = src[tid];
    __syncthreads();

    int j = tid & 63;
    int rl = tid >> 6;
    float fq = 0.f, fk = 0.f;
#pragma unroll
    for (int k = 0; k < 64; ++k) {
        float v = sIn[rl][k];
        fq = fmaf(v, sW[0][k][j], fq);
        fk = fmaf(v, sW[1][k][j], fk);
    }
    dstQ[rl * 64 + j] = fq * 0.125f;  // fold 1/sqrt(64)
    dstK[rl * 64 + j] = fk;
}

// ---------------- kernel 2: flash attention, fp32, f32x2 packed ----------------
// grid 256 blocks (0..127 = x-set, 128..255 = y-set), each block = 64 query rows.
// 256 threads: r = tid>>2 (query row 0..63), g = tid&3.
// Thread owns S columns c = g + 4*c' (c'=0..15)  -> 4 distinct banks across g.
// Thread owns O dims d = u*16 + g*4 (u=0..3)     -> 4 distinct banks across g.
__global__ __launch_bounds__(256, 2) void attn_kernel(const float* __restrict__ x,
                                                      const float* __restrict__ y) {
    __shared__ __align__(16) float Qs[64 * 68];
    __shared__ __align__(16) float Bs[64 * 68];  // K tile, then V tile (reused)

    int tid = threadIdx.x;
    int b = blockIdx.x;
    bool isx = b < 128;
    int bb = isx ? b : b - 128;
    int m0 = bb * 64;

    const float* Q = isx ? g_Qx : g_Qy;
    const float* K = isx ? g_Kx : g_Ky;
    const float* V = isx ? x : y;
    float* O = isx ? g_xatt : g_yatt;
    float* nrm = isx ? g_xnrm : g_ynrm;

    // load Q tile (row-major, stride 68)
    for (int t = tid; t < 1024; t += 256) {
        int row = t >> 4, u = t & 15;
        *(float4*)&Qs[row * 68 + u * 4] =
            *(const float4*)&Q[(size_t)(m0 + row) * 64 + u * 4];
    }

    int r = tid >> 2;
    int g = tid & 3;
    int lane = tid & 31;

    unsigned long long accd2[8];
#pragma unroll
    for (int u = 0; u < 8; ++u) accd2[u] = 0ull;
    float m_run = -CUDART_INF_F;
    float l_t = 0.f;

    for (int kt = 0; kt < 128; ++kt) {
        int n0 = kt * 64;
        __syncthreads();  // prev PV reads done
        for (int t = tid; t < 1024; t += 256) {
            int row = t >> 4, u = t & 15;
            *(float4*)&Bs[row * 68 + u * 4] =
                *(const float4*)&K[(size_t)(n0 + row) * 64 + u * 4];
        }
        __syncthreads();

        // ---- S = Q Kt^T (packed over k) ----
        unsigned long long sacc[16];
#pragma unroll
        for (int c = 0; c < 16; ++c) sacc[c] = 0ull;
        const float* qrow = &Qs[r * 68];
        const float* bbase = &Bs[g * 68];  // col row index = g + 4*c -> offset g*68 + c*272
#pragma unroll
        for (int kk = 0; kk < 64; kk += 4) {
            ulonglong2 q4 = *(const ulonglong2*)(qrow + kk);
#pragma unroll
            for (int c = 0; c < 16; ++c) {
                ulonglong2 kv = *(const ulonglong2*)(bbase + c * 272 + kk);
                sacc[c] = fma2_(q4.x, kv.x, sacc[c]);
                sacc[c] = fma2_(q4.y, kv.y, sacc[c]);
            }
        }
        float s[16];
#pragma unroll
        for (int c = 0; c < 16; ++c) {
            float2 v = up2(sacc[c]);
            s[c] = v.x + v.y;
        }

        // ---- online softmax (per-thread, row-max shared across the 4 lanes) ----
        float mt = s[0];
#pragma unroll
        for (int c = 1; c < 16; ++c) mt = fmaxf(mt, s[c]);
        mt = fmaxf(mt, __shfl_xor_sync(0xffffffffu, mt, 1));
        mt = fmaxf(mt, __shfl_xor_sync(0xffffffffu, mt, 2));
        float m_new = fmaxf(m_run, mt);
        float scale = exp2f((m_run - m_new) * LOG2E);
        l_t *= scale;
        unsigned long long sc2 = pk2(scale, scale);
#pragma unroll
        for (int u = 0; u < 8; ++u) accd2[u] = mul2_(accd2[u], sc2);
        float p[16];
#pragma unroll
        for (int c = 0; c < 16; ++c) {
            p[c] = exp2f((s[c] - m_new) * LOG2E);
            l_t += p[c];
        }
        m_run = m_new;

        __syncthreads();  // all S reads of Bs done
        for (int t = tid; t < 1024; t += 256) {
            int row = t >> 4, u = t & 15;
            *(float4*)&Bs[row * 68 + u * 4] =
                *(const float4*)&V[(size_t)(n0 + row) * 64 + u * 4];
        }
        __syncthreads();

        // ---- O += P V ---- (thread accumulates its 16 dims over all 64 cols)
#pragma unroll
        for (int c = 0; c < 64; ++c) {
            // col c is owned by lane with g' = c&3, slot c>>2
            float pc = __shfl_sync(0xffffffffu, p[c >> 2], (lane & ~3) | (c & 3));
            unsigned long long pc2 = pk2(pc, pc);
            const float* vrow = &Bs[c * 68 + g * 4];
#pragma unroll
            for (int u = 0; u < 4; ++u) {
                ulonglong2 v4 = *(const ulonglong2*)(vrow + u * 16);
                accd2[u * 2] = fma2_(pc2, v4.x, accd2[u * 2]);
                accd2[u * 2 + 1] = fma2_(pc2, v4.y, accd2[u * 2 + 1]);
            }
        }
    }

    // ---- epilogue: normalize, write O and row norms ----
    float l = l_t;
    l += __shfl_xor_sync(0xffffffffu, l, 1);
    l += __shfl_xor_sync(0xffffffffu, l, 2);
    float inv = 1.0f / l;

    float nr = 0.f;
#pragma unroll
    for (int u = 0; u < 4; ++u) {
        float2 e0 = up2(accd2[u * 2]);
        float2 e1 = up2(accd2[u * 2 + 1]);
        float o0 = e0.x * inv, o1 = e0.y * inv, o2 = e1.x * inv, o3 = e1.y * inv;
        nr = fmaf(o0, o0, nr);
        nr = fmaf(o1, o1, nr);
        nr = fmaf(o2, o2, nr);
        nr = fmaf(o3, o3, nr);
        *(float4*)&O[(size_t)(m0 + r) * 64 + u * 16 + g * 4] =
            make_float4(o0, o1, o2, o3);
    }
    nr += __shfl_xor_sync(0xffffffffu, nr, 1);
    nr += __shfl_xor_sync(0xffffffffu, nr, 2);
    if (g == 0) nrm[m0 + r] = nr;
}

// ---------------- kernel 3: RBF  out[i,j] = exp(2*dot - |x|^2 - |y|^2) ----------------
// grid (128,128), 256 threads; thread (ty=tid>>4, tx=tid&15) owns rows ty+16a, cols tx+16b.
__global__ __launch_bounds__(256) void rbf_kernel(float* __restrict__ out) {
    __shared__ __align__(16) float Xs[64 * 68];
    __shared__ __align__(16) float Ys[64 * 68];
    __shared__ float snx[64];
    __shared__ float sny[64];

    int tid = threadIdx.x;
    int it = blockIdx.y, jt = blockIdx.x;
    int i0 = it * 64, j0 = jt * 64;

    for (int t = tid; t < 1024; t += 256) {
        int row = t >> 4, u = t & 15;
        *(float4*)&Xs[row * 68 + u * 4] =
            *(const float4*)&g_xatt[(size_t)(i0 + row) * 64 + u * 4];
        *(float4*)&Ys[row * 68 + u * 4] =
            *(const float4*)&g_yatt[(size_t)(j0 + row) * 64 + u * 4];
    }
    if (tid < 64) snx[tid] = g_xnrm[i0 + tid];
    else if (tid < 128) sny[tid - 64] = g_ynrm[j0 + tid - 64];
    __syncthreads();

    int ty = tid >> 4, tx = tid & 15;

    unsigned long long acc[4][4];
#pragma unroll
    for (int a = 0; a < 4; ++a)
#pragma unroll
        for (int bq = 0; bq < 4; ++bq) acc[a][bq] = 0ull;

#pragma unroll
    for (int dd = 0; dd < 64; dd += 4) {
        ulonglong2 xv[4], yv[4];
#pragma unroll
        for (int a = 0; a < 4; ++a)
            xv[a] = *(const ulonglong2*)&Xs[(ty + 16 * a) * 68 + dd];
#pragma unroll
        for (int bq = 0; bq < 4; ++bq)
            yv[bq] = *(const ulonglong2*)&Ys[(tx + 16 * bq) * 68 + dd];
#pragma unroll
        for (int a = 0; a < 4; ++a)
#pragma unroll
            for (int bq = 0; bq < 4; ++bq) {
                acc[a][bq] = fma2_(xv[a].x, yv[bq].x, acc[a][bq]);
                acc[a][bq] = fma2_(xv[a].y, yv[bq].y, acc[a][bq]);
            }
    }

#pragma unroll
    for (int a = 0; a < 4; ++a) {
        int i = i0 + ty + 16 * a;
        float nx = snx[ty + 16 * a];
#pragma unroll
        for (int bq = 0; bq < 4; ++bq) {
            int j = j0 + tx + 16 * bq;
            float2 e = up2(acc[a][bq]);
            float dot = e.x + e.y;
            float arg = 2.0f * dot - nx - sny[tx + 16 * bq];  // = -||xi-yj||^2
            out[(size_t)i * N + j] = exp2f(arg * LOG2E);
        }
    }
}

// ---------------- launch ----------------
extern "C" void kernel_launch(void* const* d_in, const int* in_sizes, int n_in,
                              void* d_out, int out_size) {
    const float* Wq = (const float*)d_in[0];  // rotation_params
    const float* Wk = (const float*)d_in[1];  // entangle_params
    const float* x = (const float*)d_in[2];
    const float* y = (const float*)d_in[3];
    float* out = (float*)d_out;

    proj_kernel<<<(2 * N) / 4, 256>>>(x, y, Wq, Wk);
    attn_kernel<<<256, 256>>>(x, y);
    rbf_kernel<<<dim3(128, 128), 256>>>(out);
}